// round 1
// baseline (speedup 1.0000x reference)
#include <cuda_runtime.h>
#include <math.h>

// Problem constants
#define Bb 128
#define Tt 64
#define Ee 768
#define Hh 768
#define Gg 3072
// L = 2, but layer 0 is dead code (no cross-layer feed; h_last = layer 1 only).

// ---------------- device scratch (no allocations allowed) ----------------
__device__ int   g_len[Bb];
__device__ int   g_actcnt[Tt];
__device__ int   g_act[Tt * Bb];
__device__ int   g_nrows;
__device__ int   g_rows[Bb * Tt];   // packed (b<<6)|t for active (b,t)
__device__ int   g_erow[Bb * Tt];   // embedding row (token id) per active row
__device__ float g_xproj[Tt * Bb * Gg];  // [t][b][g] input projection (layer 1 only)
__device__ float g_h[Bb * Hh];
__device__ float g_c[Bb * Hh];
__device__ float g_gates[Bb * Gg];

__device__ __forceinline__ float sigf(float x) { return 1.0f / (1.0f + expf(-x)); }

// ---------------- K0: dtype detect + length/active-list setup ----------------
// JAX without x64 silently downcasts int64->int32; detect actual width on device:
// if data were int64 (little-endian), every high 32-bit word of message is 0
// (values in [0, 32000)). For int32 data, odd words are real nonzero tokens.
__global__ void k0_setup(const int* __restrict__ msg, const int* __restrict__ mlen) {
    __shared__ int s_flag;
    __shared__ int s_cnt[Tt];
    __shared__ int s_nr;
    int tid = threadIdx.x;
    if (tid == 0) { s_flag = 0; s_nr = 0; }
    if (tid < Tt) s_cnt[tid] = 0;
    __syncthreads();

    int local = 0;
    for (int i = tid; i < (Bb * Tt) / 2; i += 256)
        if (msg[2 * i + 1] != 0) local = 1;
    if (local) atomicOr(&s_flag, 1);
    __syncthreads();
    int is64 = (s_flag == 0);

    if (tid < Bb) {
        int lb = is64 ? mlen[2 * tid] : mlen[tid];
        g_len[tid] = lb;
        for (int t = 0; t < lb; t++) {
            int p = atomicAdd(&s_cnt[t], 1);
            g_act[t * Bb + p] = tid;
            int r = atomicAdd(&s_nr, 1);
            g_rows[r] = (tid << 6) | t;
            int mi = tid * Tt + t;
            g_erow[r] = is64 ? msg[2 * mi] : msg[mi];
        }
    }
    __syncthreads();
    if (tid < Tt) g_actcnt[tid] = s_cnt[tid];
    if (tid == 0) g_nrows = s_nr;
}

// ---------------- K1: input projection GEMM (active rows only) ----------------
// C[row=(b,t), n] = dot(emb_table[token], W_ih[1][n][:]) + b_ih[1][n]
// Tile: 64x64, BK=16, 256 threads, 4x4 per thread.
__global__ void k1_xproj(const float* __restrict__ embt,
                         const float* __restrict__ Wih,
                         const float* __restrict__ bih) {
    __shared__ float As[64][17];
    __shared__ float Bs[64][17];
    __shared__ int s_bt[64];
    __shared__ int s_eoff[64];

    int tid = threadIdx.x;
    int nrows = g_nrows;
    int r0 = blockIdx.x * 64;
    if (r0 >= nrows) return;
    int n0 = blockIdx.y * 64;

    if (tid < 64) {
        int r = r0 + tid;
        if (r < nrows) { s_bt[tid] = g_rows[r]; s_eoff[tid] = g_erow[r] * Ee; }
        else           { s_bt[tid] = -1;        s_eoff[tid] = 0; }
    }
    __syncthreads();

    const float* W1 = Wih + Gg * Ee;   // layer 1 slice of [L,G,E]
    int rl = tid >> 2, kq = (tid & 3) << 2;
    int ty = tid >> 4, tx = tid & 15;

    float acc[4][4];
#pragma unroll
    for (int i = 0; i < 4; i++)
#pragma unroll
        for (int j = 0; j < 4; j++) acc[i][j] = 0.0f;

    for (int kk = 0; kk < Ee; kk += 16) {
        float4 av = *(const float4*)(embt + s_eoff[rl] + kk + kq);
        float4 bv = *(const float4*)(W1 + (n0 + rl) * Ee + kk + kq);
        As[rl][kq + 0] = av.x; As[rl][kq + 1] = av.y; As[rl][kq + 2] = av.z; As[rl][kq + 3] = av.w;
        Bs[rl][kq + 0] = bv.x; Bs[rl][kq + 1] = bv.y; Bs[rl][kq + 2] = bv.z; Bs[rl][kq + 3] = bv.w;
        __syncthreads();
#pragma unroll
        for (int k = 0; k < 16; k++) {
            float a[4], b[4];
#pragma unroll
            for (int i = 0; i < 4; i++) a[i] = As[ty * 4 + i][k];
#pragma unroll
            for (int j = 0; j < 4; j++) b[j] = Bs[tx * 4 + j][k];
#pragma unroll
            for (int i = 0; i < 4; i++)
#pragma unroll
                for (int j = 0; j < 4; j++) acc[i][j] = fmaf(a[i], b[j], acc[i][j]);
        }
        __syncthreads();
    }

#pragma unroll
    for (int i = 0; i < 4; i++) {
        int meta = s_bt[ty * 4 + i];
        if (meta < 0) continue;
        int b = meta >> 6, t = meta & 63;
        float* dst = g_xproj + ((t * Bb) + b) * Gg + n0;
#pragma unroll
        for (int j = 0; j < 4; j++) {
            int n = tx * 4 + j;
            dst[n] = acc[i][j] + bih[Gg + n0 + n];
        }
    }
}

// ---------------- K2: recurrent gate GEMM for step t (active batches only) ----
// gates[b, n] = xproj[t,b,n] + dot(h_prev[b,:], W_hh[1][n][:]) + b_hh[1][n]
// Tile: 32(M) x 64(N), BK=32, 256 threads, 2x4 per thread.
__global__ void k2_gates(int t,
                         const float* __restrict__ Whh,
                         const float* __restrict__ bhh) {
    int cnt = g_actcnt[t];
    int m0 = blockIdx.x * 32;
    if (m0 >= cnt) return;
    int n0 = blockIdx.y * 64;

    __shared__ float As[32][33];
    __shared__ float Bs[64][33];
    __shared__ int s_b[32];

    int tid = threadIdx.x;
    if (tid < 32) {
        int mi = m0 + tid;
        s_b[tid] = (mi < cnt) ? g_act[t * Bb + mi] : -1;
    }
    __syncthreads();

    const float* W1 = Whh + Gg * Hh;   // layer 1 slice of [L,G,H]
    int rl = tid >> 3, kq = (tid & 7) << 2;
    int ty = tid >> 4, tx = tid & 15;
    int hoff = (s_b[rl] < 0 ? 0 : s_b[rl]) * Hh;

    float acc[2][4];
#pragma unroll
    for (int i = 0; i < 2; i++)
#pragma unroll
        for (int j = 0; j < 4; j++) acc[i][j] = 0.0f;

    for (int kk = 0; kk < Hh; kk += 32) {
        float4 av  = *(const float4*)(g_h + hoff + kk + kq);
        float4 bv0 = *(const float4*)(W1 + (n0 + rl) * Hh + kk + kq);
        float4 bv1 = *(const float4*)(W1 + (n0 + rl + 32) * Hh + kk + kq);
        As[rl][kq + 0] = av.x;  As[rl][kq + 1] = av.y;  As[rl][kq + 2] = av.z;  As[rl][kq + 3] = av.w;
        Bs[rl][kq + 0] = bv0.x; Bs[rl][kq + 1] = bv0.y; Bs[rl][kq + 2] = bv0.z; Bs[rl][kq + 3] = bv0.w;
        Bs[rl + 32][kq + 0] = bv1.x; Bs[rl + 32][kq + 1] = bv1.y; Bs[rl + 32][kq + 2] = bv1.z; Bs[rl + 32][kq + 3] = bv1.w;
        __syncthreads();
#pragma unroll
        for (int k = 0; k < 32; k++) {
            float a[2], b[4];
#pragma unroll
            for (int i = 0; i < 2; i++) a[i] = As[ty * 2 + i][k];
#pragma unroll
            for (int j = 0; j < 4; j++) b[j] = Bs[tx * 4 + j][k];
#pragma unroll
            for (int i = 0; i < 2; i++)
#pragma unroll
                for (int j = 0; j < 4; j++) acc[i][j] = fmaf(a[i], b[j], acc[i][j]);
        }
        __syncthreads();
    }

#pragma unroll
    for (int i = 0; i < 2; i++) {
        int b = s_b[ty * 2 + i];
        if (b < 0) continue;
        const float* xp = g_xproj + ((t * Bb) + b) * Gg + n0;
        float* gg = g_gates + b * Gg + n0;
#pragma unroll
        for (int j = 0; j < 4; j++) {
            int n = tx * 4 + j;
            gg[n] = acc[i][j] + xp[n] + bhh[Gg + n0 + n];
        }
    }
}

// ---------------- K3: LSTM cell + dual layernorm for step t -------------------
__global__ void k3_cell(int t,
                        const float* __restrict__ gamma_h, const float* __restrict__ beta_h,
                        const float* __restrict__ gamma_c, const float* __restrict__ beta_c,
                        float* __restrict__ out) {
    int m = blockIdx.x;
    int cnt = g_actcnt[t];
    if (m >= cnt) return;
    int b = g_act[t * Bb + m];
    int tid = threadIdx.x;

    __shared__ float sh[Hh];
    __shared__ float sc[Hh];
    __shared__ float4 red[256];

    float ph = 0.f, ph2 = 0.f, pc = 0.f, pc2 = 0.f;
    const float* gbase = g_gates + b * Gg;
    for (int j = tid; j < Hh; j += 256) {
        float ig = gbase[j];
        float fg = gbase[Hh + j];
        float gg = gbase[2 * Hh + j];
        float og = gbase[3 * Hh + j];
        float cprev = g_c[b * Hh + j];
        float cn = sigf(fg) * cprev + sigf(ig) * tanhf(gg);
        float hr = sigf(og) * tanhf(cn);
        sh[j] = hr; sc[j] = cn;
        ph += hr; ph2 += hr * hr; pc += cn; pc2 += cn * cn;
    }
    red[tid] = make_float4(ph, ph2, pc, pc2);
    __syncthreads();
    for (int s = 128; s > 0; s >>= 1) {
        if (tid < s) {
            float4 o = red[tid + s];
            float4 me = red[tid];
            me.x += o.x; me.y += o.y; me.z += o.z; me.w += o.w;
            red[tid] = me;
        }
        __syncthreads();
    }
    float4 tot = red[0];
    float inv_n = 1.0f / (float)Hh;
    float mu_h = tot.x * inv_n;
    float var_h = tot.y * inv_n - mu_h * mu_h;
    float mu_c = tot.z * inv_n;
    float var_c = tot.w * inv_n - mu_c * mu_c;
    float rs_h = rsqrtf(var_h + 1e-5f);
    float rs_c = rsqrtf(var_c + 1e-5f);

    bool is_last = (t == g_len[b] - 1);
    for (int j = tid; j < Hh; j += 256) {
        float hv = (sh[j] - mu_h) * rs_h * gamma_h[j] + beta_h[j];
        float cv = (sc[j] - mu_c) * rs_c * gamma_c[j] + beta_c[j];
        g_h[b * Hh + j] = hv;
        g_c[b * Hh + j] = cv;
        if (is_last) out[b * Hh + j] = hv;
    }
}

// ---------------- host launcher (graph-capturable) ----------------------------
extern "C" void kernel_launch(void* const* d_in, const int* in_sizes, int n_in,
                              void* d_out, int out_size) {
    const int*   msg  = (const int*)d_in[0];
    const int*   mlen = (const int*)d_in[1];
    const float* embt = (const float*)d_in[2];
    const float* Wih  = (const float*)d_in[3];
    const float* Whh  = (const float*)d_in[4];
    const float* bih  = (const float*)d_in[5];
    const float* bhh  = (const float*)d_in[6];
    const float* gmh  = (const float*)d_in[7];
    const float* bth  = (const float*)d_in[8];
    const float* gmc  = (const float*)d_in[9];
    const float* btc  = (const float*)d_in[10];
    float* out = (float*)d_out;

    void* hp; cudaGetSymbolAddress(&hp, g_h);
    void* cp; cudaGetSymbolAddress(&cp, g_c);
    cudaMemsetAsync(hp, 0, Bb * Hh * sizeof(float));
    cudaMemsetAsync(cp, 0, Bb * Hh * sizeof(float));

    k0_setup<<<1, 256>>>(msg, mlen);
    k1_xproj<<<dim3(Bb * Tt / 64, Gg / 64), 256>>>(embt, Wih, bih);
    for (int t = 0; t < Tt; t++) {
        k2_gates<<<dim3(Bb / 32, Gg / 64), 256>>>(t, Whh, bhh);
        k3_cell<<<Bb, 256>>>(t, gmh, bth, gmc, btc, out);
    }
}